// round 2
// baseline (speedup 1.0000x reference)
#include <cuda_runtime.h>

// Problem constants
#define B_  4
#define T_  2048
#define C_  1024
#define H_  2048
#define M_  (B_*T_)          // 8192 rows for QKV projection
#define SCALE_ (0.03125f)    // 1024^-0.5 = 1/32

// GEMM tiling
#define BM 64
#define BN 64
#define BK 16
#define TM 4
#define TN 4
#define NTHREADS 256

// Scratch (static device globals — no runtime allocation allowed)
__device__ float g_q[M_ * H_];        // 64 MB
__device__ float g_k[M_ * H_];        // 64 MB
__device__ float g_v[M_ * H_];        // 64 MB
__device__ float g_s[B_ * T_ * T_];   // 64 MB  (attention scores / probs)

// ---------------------------------------------------------------------------
// Tiled fp32 GEMM block: C[row0:+64, col0:+64] = scale * A·B (+bias)
// BT=false: B is [K, N] row-major (NN). BT=true: B is [N, K] row-major (NT).
// All dims are multiples of the tile sizes; no bounds checks needed.
// ---------------------------------------------------------------------------
template<bool BT>
__device__ __forceinline__ void gemm_block(
    const float* __restrict__ A, int lda,
    const float* __restrict__ Bm, int ldb,
    float* __restrict__ Cm, int ldc,
    int row0, int col0, int ktiles,
    const float* __restrict__ bias, float scale)
{
    __shared__ float As[BK][BM + 4];
    __shared__ float Bs[BK][BN + 4];

    const int tid   = threadIdx.x;          // 256 threads
    const int a_row = tid >> 2;             // 0..63
    const int a_col = (tid & 3) << 2;       // 0,4,8,12
    const int b_row = tid >> 4;             // 0..15
    const int b_col = (tid & 15) << 2;      // 0..60
    const int tr    = (tid >> 4) << 2;      // 0..60 (micro-tile row)
    const int tc    = (tid & 15) << 2;      // 0..60 (micro-tile col)

    float acc[TM][TN];
    #pragma unroll
    for (int i = 0; i < TM; i++)
        #pragma unroll
        for (int j = 0; j < TN; j++) acc[i][j] = 0.0f;

    for (int kt = 0; kt < ktiles; kt++) {
        const int k0 = kt * BK;

        // Load A tile [BM x BK], store transposed As[k][m]
        float4 av = *reinterpret_cast<const float4*>(
            A + (size_t)(row0 + a_row) * lda + k0 + a_col);
        As[a_col + 0][a_row] = av.x;
        As[a_col + 1][a_row] = av.y;
        As[a_col + 2][a_row] = av.z;
        As[a_col + 3][a_row] = av.w;

        if (BT) {
            // B tile rows are output columns: [BN x BK] -> Bs[k][n]
            float4 bv = *reinterpret_cast<const float4*>(
                Bm + (size_t)(col0 + a_row) * ldb + k0 + a_col);
            Bs[a_col + 0][a_row] = bv.x;
            Bs[a_col + 1][a_row] = bv.y;
            Bs[a_col + 2][a_row] = bv.z;
            Bs[a_col + 3][a_row] = bv.w;
        } else {
            // B tile [BK x BN] -> Bs[k][n] directly
            float4 bv = *reinterpret_cast<const float4*>(
                Bm + (size_t)(k0 + b_row) * ldb + col0 + b_col);
            *reinterpret_cast<float4*>(&Bs[b_row][b_col]) = bv;
        }
        __syncthreads();

        #pragma unroll
        for (int kk = 0; kk < BK; kk++) {
            float4 a4 = *reinterpret_cast<const float4*>(&As[kk][tr]);
            float4 b4 = *reinterpret_cast<const float4*>(&Bs[kk][tc]);
            float a[4] = {a4.x, a4.y, a4.z, a4.w};
            float b[4] = {b4.x, b4.y, b4.z, b4.w};
            #pragma unroll
            for (int i = 0; i < 4; i++)
                #pragma unroll
                for (int j = 0; j < 4; j++)
                    acc[i][j] = fmaf(a[i], b[j], acc[i][j]);
        }
        __syncthreads();
    }

    // Epilogue: scale, optional bias, vectorized store
    float4 bvv = make_float4(0.f, 0.f, 0.f, 0.f);
    if (bias) bvv = *reinterpret_cast<const float4*>(bias + col0 + tc);
    #pragma unroll
    for (int i = 0; i < TM; i++) {
        float4 o;
        o.x = fmaf(acc[i][0], scale, bvv.x);
        o.y = fmaf(acc[i][1], scale, bvv.y);
        o.z = fmaf(acc[i][2], scale, bvv.z);
        o.w = fmaf(acc[i][3], scale, bvv.w);
        *reinterpret_cast<float4*>(
            Cm + (size_t)(row0 + tr + i) * ldc + col0 + tc) = o;
    }
}

// ---------------------------------------------------------------------------
// 1) QKV projection: grid.z selects Q/K/V weights; shares x tiles via L2
// ---------------------------------------------------------------------------
__global__ void qkv_kernel(const float* __restrict__ x,
                           const float* __restrict__ Wq, const float* __restrict__ bq,
                           const float* __restrict__ Wk, const float* __restrict__ bk,
                           const float* __restrict__ Wv, const float* __restrict__ bv)
{
    const float* W; const float* bias; float* out;
    if (blockIdx.z == 0)      { W = Wq; bias = bq; out = g_q; }
    else if (blockIdx.z == 1) { W = Wk; bias = bk; out = g_k; }
    else                      { W = Wv; bias = bv; out = g_v; }

    const int row0 = blockIdx.y * BM;
    const int col0 = blockIdx.x * BN;
    gemm_block<false>(x, C_, W, H_, out, H_, row0, col0, C_ / BK, bias, 1.0f);
}

// ---------------------------------------------------------------------------
// 2) S = scale * Q · K^T  (NT GEMM, per batch; skip strictly-upper blocks)
// ---------------------------------------------------------------------------
__global__ void qk_kernel()
{
    const int b    = blockIdx.z;
    const int row0 = blockIdx.y * BM;
    const int col0 = blockIdx.x * BN;
    if (col0 >= row0 + BM) return;   // entirely above the causal diagonal: unused

    const float* Q = g_q + (size_t)b * T_ * H_;
    const float* K = g_k + (size_t)b * T_ * H_;
    float*       S = g_s + (size_t)b * T_ * T_;
    gemm_block<true>(Q, H_, K, H_, S, T_, row0, col0, H_ / BK, nullptr, SCALE_);
}

// ---------------------------------------------------------------------------
// 3) Causal softmax, in place on S. One block per (row, batch).
//    Reads only j <= i; writes zeros for j > i (needed by PV k-limit trick).
// ---------------------------------------------------------------------------
__global__ void softmax_kernel()
{
    const int i = blockIdx.x;
    const int b = blockIdx.y;
    float* row = g_s + ((size_t)b * T_ + i) * T_;
    const int n   = i + 1;
    const int tid = threadIdx.x;

    __shared__ float red[8];
    __shared__ float bc;

    // --- row max over [0, n) ---
    float m = -1e30f;
    for (int j = tid; j < n; j += NTHREADS) m = fmaxf(m, row[j]);
    #pragma unroll
    for (int o = 16; o; o >>= 1) m = fmaxf(m, __shfl_xor_sync(0xffffffffu, m, o));
    if ((tid & 31) == 0) red[tid >> 5] = m;
    __syncthreads();
    if (tid == 0) {
        float v = red[0];
        #pragma unroll
        for (int w = 1; w < 8; w++) v = fmaxf(v, red[w]);
        bc = v;
    }
    __syncthreads();
    m = bc;

    // --- exp and row sum ---
    float s = 0.0f;
    for (int j = tid; j < n; j += NTHREADS) {
        float e = __expf(row[j] - m);
        row[j] = e;
        s += e;
    }
    #pragma unroll
    for (int o = 16; o; o >>= 1) s += __shfl_xor_sync(0xffffffffu, s, o);
    __syncthreads();                 // red[] reuse
    if ((tid & 31) == 0) red[tid >> 5] = s;
    __syncthreads();
    if (tid == 0) {
        float v = 0.0f;
        #pragma unroll
        for (int w = 0; w < 8; w++) v += red[w];
        bc = 1.0f / v;
    }
    __syncthreads();
    const float inv = bc;

    // --- normalize + zero-fill the masked tail ---
    for (int j = tid; j < T_; j += NTHREADS)
        row[j] = (j < n) ? row[j] * inv : 0.0f;
}

// ---------------------------------------------------------------------------
// 4) O = P · V  (NN GEMM per batch). Causal: P[i,j]=0 for j>i, so the k-loop
//    only needs j < row_block_end -> ~2x work saved.
// ---------------------------------------------------------------------------
__global__ void pv_kernel(float* __restrict__ out)
{
    const int b    = blockIdx.z;
    const int row0 = blockIdx.y * BM;
    const int col0 = blockIdx.x * BN;

    const float* P = g_s + (size_t)b * T_ * T_;
    const float* V = g_v + (size_t)b * T_ * H_;
    float*       O = out + (size_t)b * T_ * H_;

    const int ktiles = (row0 + BM) / BK;   // covers all j <= i for rows in block
    gemm_block<false>(P, T_, V, H_, O, H_, row0, col0, ktiles, nullptr, 1.0f);
}

// ---------------------------------------------------------------------------
extern "C" void kernel_launch(void* const* d_in, const int* in_sizes, int n_in,
                              void* d_out, int out_size)
{
    const float* x  = (const float*)d_in[0];
    const float* Wq = (const float*)d_in[1];
    const float* bq = (const float*)d_in[2];
    const float* Wk = (const float*)d_in[3];
    const float* bk = (const float*)d_in[4];
    const float* Wv = (const float*)d_in[5];
    const float* bv = (const float*)d_in[6];
    float* out = (float*)d_out;

    dim3 blk(NTHREADS);

    qkv_kernel<<<dim3(H_ / BN, M_ / BM, 3), blk>>>(x, Wq, bq, Wk, bk, Wv, bv);
    qk_kernel<<<dim3(T_ / BN, T_ / BM, B_), blk>>>();
    softmax_kernel<<<dim3(T_, B_), blk>>>();
    pv_kernel<<<dim3(H_ / BN, T_ / BM, B_), blk>>>(out);
}

// round 3
// speedup vs baseline: 2.9074x; 2.9074x over previous
#include <cuda_runtime.h>
#include <cstdint>

// Problem constants
#define B_  4
#define T_  2048
#define C_  1024
#define H_  2048
#define M_  (B_*T_)
#define SCALE_ 0.03125f   // 1024^-0.5

// GEMM tiling
#define BM 128
#define BN 128
#define BK 16
#define LDS_S 136         // BM + 8 ; 136 mod 32 == 8 (conflict analysis depends on this)
#define NTHREADS 256

// Scratch (static device globals)
__device__ float g_q[M_ * H_];
__device__ float g_k[M_ * H_];
__device__ float g_v[M_ * H_];
__device__ float g_s[(size_t)B_ * T_ * T_];

// Round-to-nearest tf32 (unbiased; truncation would bias dots by ~1e-3)
__device__ __forceinline__ float f2tf(float f) {
    uint32_t u;
    asm("cvt.rna.tf32.f32 %0, %1;" : "=r"(u) : "f"(f));
    return __uint_as_float(u);
}

__device__ __forceinline__ void mma_tf32(float* c, const uint32_t* a, const uint32_t* b) {
    asm volatile(
        "mma.sync.aligned.m16n8k8.row.col.f32.tf32.tf32.f32 "
        "{%0,%1,%2,%3}, {%4,%5,%6,%7}, {%8,%9}, {%0,%1,%2,%3};"
        : "+f"(c[0]), "+f"(c[1]), "+f"(c[2]), "+f"(c[3])
        : "r"(a[0]), "r"(a[1]), "r"(a[2]), "r"(a[3]), "r"(b[0]), "r"(b[1]));
}

// XOR swizzle on the m/n index keyed by k bits [3:2] -> conflict-free frag loads
#define SW(idx, k) ((idx) ^ ((((k) >> 2) & 3) << 3))

// ---------------------------------------------------------------------------
// Tensor-core tiled GEMM block: C[row0:+128, col0:+128] = scale*A.B (+bias)
// BT=false: B is [K,N] row-major (NN). BT=true: B is [N,K] row-major (NT).
// ---------------------------------------------------------------------------
template<bool BT>
__device__ __forceinline__ void gemm_mma(
    const float* __restrict__ A, int lda,
    const float* __restrict__ Bm, int ldb,
    float* __restrict__ Cm, int ldc,
    int row0, int col0, int ktiles,
    const float* __restrict__ bias, float scale)
{
    __shared__ float As[2][BK][LDS_S];
    __shared__ float Bs[2][BK][LDS_S];

    const int tid  = threadIdx.x;
    const int lane = tid & 31;
    const int warp = tid >> 5;
    const int wm   = warp & 3;        // 4 warps along M (32 rows each)
    const int wn   = warp >> 2;       // 2 warps along N (64 cols each)

    // global->smem staging mapping
    const int ar = tid >> 2;          // 0..63  (A / NT-B rows)
    const int ac = (tid & 3) << 2;    // 0,4,8,12 (k within BK)
    const int br = tid >> 4;          // 0..15  (NN-B k rows)
    const int bc = (tid & 15) << 2;   // 0..60  (NN-B cols)

    float acc[2][8][4];
    #pragma unroll
    for (int i = 0; i < 2; i++)
        #pragma unroll
        for (int j = 0; j < 8; j++)
            #pragma unroll
            for (int l = 0; l < 4; l++) acc[i][j][l] = 0.0f;

    float4 sa0, sa1, sb0, sb1;

    auto load_tile = [&](int k0) {
        sa0 = *(const float4*)(A + (size_t)(row0 + ar)      * lda + k0 + ac);
        sa1 = *(const float4*)(A + (size_t)(row0 + ar + 64) * lda + k0 + ac);
        if (BT) {
            sb0 = *(const float4*)(Bm + (size_t)(col0 + ar)      * ldb + k0 + ac);
            sb1 = *(const float4*)(Bm + (size_t)(col0 + ar + 64) * ldb + k0 + ac);
        } else {
            sb0 = *(const float4*)(Bm + (size_t)(k0 + br) * ldb + col0 + bc);
            sb1 = *(const float4*)(Bm + (size_t)(k0 + br) * ldb + col0 + bc + 64);
        }
    };

    auto store_tile = [&](int buf) {
        const float* a0 = (const float*)&sa0;
        const float* a1 = (const float*)&sa1;
        const float* b0 = (const float*)&sb0;
        const float* b1 = (const float*)&sb1;
        #pragma unroll
        for (int j = 0; j < 4; j++) {
            const int k = ac + j;
            As[buf][k][SW(ar,      k)] = f2tf(a0[j]);
            As[buf][k][SW(ar + 64, k)] = f2tf(a1[j]);
        }
        if (BT) {
            #pragma unroll
            for (int j = 0; j < 4; j++) {
                const int k = ac + j;
                Bs[buf][k][SW(ar,      k)] = f2tf(b0[j]);
                Bs[buf][k][SW(ar + 64, k)] = f2tf(b1[j]);
            }
        } else {
            #pragma unroll
            for (int j = 0; j < 4; j++) {
                Bs[buf][br][SW(bc + j,      br)] = f2tf(b0[j]);
                Bs[buf][br][SW(bc + 64 + j, br)] = f2tf(b1[j]);
            }
        }
    };

    auto compute = [&](int buf) {
        const int c = lane & 3, g = lane >> 2;
        #pragma unroll
        for (int ks = 0; ks < 2; ks++) {
            const int k0 = ks * 8;
            uint32_t af[2][4], bf[8][2];
            #pragma unroll
            for (int mi = 0; mi < 2; mi++) {
                const int r = wm * 32 + mi * 16 + g;
                af[mi][0] = __float_as_uint(As[buf][k0 + c    ][SW(r,     k0 + c    )]);
                af[mi][1] = __float_as_uint(As[buf][k0 + c    ][SW(r + 8, k0 + c    )]);
                af[mi][2] = __float_as_uint(As[buf][k0 + c + 4][SW(r,     k0 + c + 4)]);
                af[mi][3] = __float_as_uint(As[buf][k0 + c + 4][SW(r + 8, k0 + c + 4)]);
            }
            #pragma unroll
            for (int ni = 0; ni < 8; ni++) {
                const int col = wn * 64 + ni * 8 + g;
                bf[ni][0] = __float_as_uint(Bs[buf][k0 + c    ][SW(col, k0 + c    )]);
                bf[ni][1] = __float_as_uint(Bs[buf][k0 + c + 4][SW(col, k0 + c + 4)]);
            }
            #pragma unroll
            for (int mi = 0; mi < 2; mi++)
                #pragma unroll
                for (int ni = 0; ni < 8; ni++)
                    mma_tf32(acc[mi][ni], af[mi], bf[ni]);
        }
    };

    // software-pipelined main loop, double-buffered smem
    load_tile(0);
    store_tile(0);
    __syncthreads();
    int buf = 0;
    for (int kt = 0; kt < ktiles; kt++) {
        const bool has_next = (kt + 1 < ktiles);
        if (has_next) load_tile((kt + 1) * BK);
        compute(buf);
        if (has_next) store_tile(buf ^ 1);
        __syncthreads();
        buf ^= 1;
    }

    // epilogue
    const int g  = lane >> 2;
    const int cc = (lane & 3) * 2;
    #pragma unroll
    for (int mi = 0; mi < 2; mi++) {
        const int r0g = row0 + wm * 32 + mi * 16 + g;
        #pragma unroll
        for (int ni = 0; ni < 8; ni++) {
            const int col = col0 + wn * 64 + ni * 8 + cc;
            float bx = 0.f, by = 0.f;
            if (bias) { bx = bias[col]; by = bias[col + 1]; }
            float2 o0 = make_float2(fmaf(acc[mi][ni][0], scale, bx),
                                    fmaf(acc[mi][ni][1], scale, by));
            float2 o1 = make_float2(fmaf(acc[mi][ni][2], scale, bx),
                                    fmaf(acc[mi][ni][3], scale, by));
            *(float2*)(Cm + (size_t)r0g       * ldc + col) = o0;
            *(float2*)(Cm + (size_t)(r0g + 8) * ldc + col) = o1;
        }
    }
}

// ---------------------------------------------------------------------------
// 1) QKV projection
// ---------------------------------------------------------------------------
__global__ void __launch_bounds__(NTHREADS)
qkv_kernel(const float* __restrict__ x,
           const float* __restrict__ Wq, const float* __restrict__ bq,
           const float* __restrict__ Wk, const float* __restrict__ bk,
           const float* __restrict__ Wv, const float* __restrict__ bv)
{
    const float* W; const float* bias; float* out;
    if (blockIdx.z == 0)      { W = Wq; bias = bq; out = g_q; }
    else if (blockIdx.z == 1) { W = Wk; bias = bk; out = g_k; }
    else                      { W = Wv; bias = bv; out = g_v; }

    gemm_mma<false>(x, C_, W, H_, out, H_,
                    blockIdx.y * BM, blockIdx.x * BN, C_ / BK, bias, 1.0f);
}

// ---------------------------------------------------------------------------
// 2) S = scale * Q.K^T  (NT, per batch; skip blocks above the causal diagonal)
// ---------------------------------------------------------------------------
__global__ void __launch_bounds__(NTHREADS)
qk_kernel()
{
    const int b    = blockIdx.z;
    const int row0 = blockIdx.y * BM;
    const int col0 = blockIdx.x * BN;
    if (col0 >= row0 + BM) return;

    const float* Q = g_q + (size_t)b * T_ * H_;
    const float* K = g_k + (size_t)b * T_ * H_;
    float*       S = g_s + (size_t)b * T_ * T_;
    gemm_mma<true>(Q, H_, K, H_, S, T_, row0, col0, H_ / BK, nullptr, SCALE_);
}

// ---------------------------------------------------------------------------
// 3) Causal softmax in place on S (zero-fills j > i for the PV k-limit trick)
// ---------------------------------------------------------------------------
__global__ void __launch_bounds__(NTHREADS)
softmax_kernel()
{
    const int i = blockIdx.x;
    const int b = blockIdx.y;
    float* row = g_s + ((size_t)b * T_ + i) * T_;
    const int n   = i + 1;
    const int tid = threadIdx.x;

    __shared__ float red[8];
    __shared__ float bcv;

    float m = -1e30f;
    for (int j = tid; j < n; j += NTHREADS) m = fmaxf(m, row[j]);
    #pragma unroll
    for (int o = 16; o; o >>= 1) m = fmaxf(m, __shfl_xor_sync(0xffffffffu, m, o));
    if ((tid & 31) == 0) red[tid >> 5] = m;
    __syncthreads();
    if (tid == 0) {
        float v = red[0];
        #pragma unroll
        for (int w = 1; w < 8; w++) v = fmaxf(v, red[w]);
        bcv = v;
    }
    __syncthreads();
    m = bcv;

    float s = 0.0f;
    for (int j = tid; j < n; j += NTHREADS) {
        float e = __expf(row[j] - m);
        row[j] = e;
        s += e;
    }
    #pragma unroll
    for (int o = 16; o; o >>= 1) s += __shfl_xor_sync(0xffffffffu, s, o);
    __syncthreads();
    if ((tid & 31) == 0) red[tid >> 5] = s;
    __syncthreads();
    if (tid == 0) {
        float v = 0.0f;
        #pragma unroll
        for (int w = 0; w < 8; w++) v += red[w];
        bcv = 1.0f / v;
    }
    __syncthreads();
    const float inv = bcv;

    for (int j = tid; j < T_; j += NTHREADS)
        row[j] = (j < n) ? row[j] * inv : 0.0f;
}

// ---------------------------------------------------------------------------
// 4) O = P.V (NN, per batch; k-loop truncated past the causal diagonal)
// ---------------------------------------------------------------------------
__global__ void __launch_bounds__(NTHREADS)
pv_kernel(float* __restrict__ out)
{
    const int b    = blockIdx.z;
    const int row0 = blockIdx.y * BM;
    const int col0 = blockIdx.x * BN;

    const float* P = g_s + (size_t)b * T_ * T_;
    const float* V = g_v + (size_t)b * T_ * H_;
    float*       O = out + (size_t)b * T_ * H_;

    gemm_mma<false>(P, T_, V, H_, O, H_,
                    row0, col0, (row0 + BM) / BK, nullptr, 1.0f);
}

// ---------------------------------------------------------------------------
extern "C" void kernel_launch(void* const* d_in, const int* in_sizes, int n_in,
                              void* d_out, int out_size)
{
    const float* x  = (const float*)d_in[0];
    const float* Wq = (const float*)d_in[1];
    const float* bq = (const float*)d_in[2];
    const float* Wk = (const float*)d_in[3];
    const float* bk = (const float*)d_in[4];
    const float* Wv = (const float*)d_in[5];
    const float* bv = (const float*)d_in[6];
    float* out = (float*)d_out;

    dim3 blk(NTHREADS);

    qkv_kernel<<<dim3(H_ / BN, M_ / BM, 3), blk>>>(x, Wq, bq, Wk, bk, Wv, bv);
    qk_kernel<<<dim3(T_ / BN, T_ / BM, B_), blk>>>();
    softmax_kernel<<<dim3(T_, B_), blk>>>();
    pv_kernel<<<dim3(H_ / BN, T_ / BM, B_), blk>>>(out);
}

// round 7
// speedup vs baseline: 7.0477x; 2.4241x over previous
#include <cuda_runtime.h>
#include <cuda_fp16.h>
#include <cstdint>

// Problem constants
#define B_  4
#define T_  2048
#define C_  1024
#define H_  2048
#define M_  (B_*T_)
#define SCALE_ 0.03125f   // 1024^-0.5

// Tiling: CTA 128x128, K-tile 64 halves; 8 warps as 4(M) x 2(N), warp 32x64
#define BKH 64
#define ASTR 72            // smem row pitch in halves (144B) -> conflict-free frags
#define NTHREADS 256

// smem stage offsets (bytes): A,B per stage = 128*144 = 18432
#define SA0 0
#define SB0 18432
#define SA1 36864
#define SB1 55296
#define SMEM_BYTES 73728
#define TSTR 136           // epilogue transpose tile pitch (halves)

// Scratch (static device globals, 16B-aligned for vector access)
__device__ __align__(256) __half g_xh [(size_t)M_ * C_];
__device__ __align__(256) __half g_wth[(size_t)3  * H_ * C_];  // W^T [z][H][C]
__device__ __align__(256) __half g_qh [(size_t)M_ * H_];
__device__ __align__(256) __half g_kh [(size_t)M_ * H_];
__device__ __align__(256) __half g_vth[(size_t)B_ * H_ * T_];  // V^T [b][H][T]
__device__ __align__(256) float  g_s  [(size_t)B_ * T_ * T_];  // scores fp32
__device__ __align__(256) __half g_p  [(size_t)B_ * T_ * T_];  // probs fp16

// ---------------------------------------------------------------------------
__device__ __forceinline__ uint32_t smem_u32(const void* p) {
    uint32_t a;
    asm("{ .reg .u64 t; cvta.to.shared.u64 t, %1; cvt.u32.u64 %0, t; }"
        : "=r"(a) : "l"(p));
    return a;
}
__device__ __forceinline__ uint32_t lds32(uint32_t a) {
    uint32_t v;
    asm volatile("ld.shared.b32 %0, [%1];" : "=r"(v) : "r"(a));
    return v;
}
__device__ __forceinline__ void cpasync16(uint32_t dst, const void* src) {
    asm volatile("cp.async.cg.shared.global [%0], [%1], 16;"
                 :: "r"(dst), "l"(src) : "memory");
}
__device__ __forceinline__ void mma16816(float* c, const uint32_t* a, const uint32_t* b) {
    asm volatile(
        "mma.sync.aligned.m16n8k16.row.col.f32.f16.f16.f32 "
        "{%0,%1,%2,%3}, {%4,%5,%6,%7}, {%8,%9}, {%0,%1,%2,%3};"
        : "+f"(c[0]), "+f"(c[1]), "+f"(c[2]), "+f"(c[3])
        : "r"(a[0]), "r"(a[1]), "r"(a[2]), "r"(a[3]), "r"(b[0]), "r"(b[1]));
}

// ---------------------------------------------------------------------------
// NT fp16 GEMM: acc = A[row0:+128, k] . B[col0:+128, k]^T over ktiles*64 k's.
// OUT=0: float out, *scale (qk / pv).  OUT=1: half out, +bias (q/k proj).
// OUT=2: half out transposed through smem (V^T), +bias.
// ---------------------------------------------------------------------------
template<int OUT>
__device__ void gemm_h(const __half* __restrict__ A, int lda,
                       const __half* __restrict__ Bm, int ldb,
                       void* __restrict__ Cptr, int ldc,
                       int row0, int col0, int ktiles,
                       const float* __restrict__ bias, float scale)
{
    extern __shared__ char dsm[];
    const uint32_t sb = smem_u32(dsm);
    const int tid  = threadIdx.x;
    const int lane = tid & 31;
    const int warp = tid >> 5;
    const int wm   = warp & 3;        // M quadrant (32 rows)
    const int wn   = warp >> 2;       // N half (64 cols)
    const int g    = lane >> 2;
    const int c    = lane & 3;

    float acc[2][8][4];
    #pragma unroll
    for (int i = 0; i < 2; i++)
        #pragma unroll
        for (int j = 0; j < 8; j++)
            #pragma unroll
            for (int l = 0; l < 4; l++) acc[i][j][l] = 0.0f;

    auto stage = [&](int kt, int s) {
        const uint32_t sa  = sb + (s ? SA1 : SA0);
        const uint32_t sbb = sb + (s ? SB1 : SB0);
        const int k0 = kt * BKH;
        #pragma unroll
        for (int i = 0; i < 4; i++) {
            const int idx = i * 256 + tid;   // 0..1023
            const int r   = idx >> 3;        // 0..127
            const int ch  = idx & 7;         // 16B chunk within 64-half row
            cpasync16(sa  + r * 144 + ch * 16,
                      A  + (size_t)(row0 + r) * lda + k0 + ch * 8);
            cpasync16(sbb + r * 144 + ch * 16,
                      Bm + (size_t)(col0 + r) * ldb + k0 + ch * 8);
        }
        asm volatile("cp.async.commit_group;" ::: "memory");
    };

    auto compute = [&](int s) {
        const uint32_t sa  = sb + (s ? SA1 : SA0);
        const uint32_t sbb = sb + (s ? SB1 : SB0);
        #pragma unroll
        for (int kk = 0; kk < 4; kk++) {           // 4 x k16
            const uint32_t koff = (kk * 16 + 2 * c) * 2;   // bytes
            uint32_t af[2][4], bf[8][2];
            #pragma unroll
            for (int mi = 0; mi < 2; mi++) {
                const uint32_t rb = sa + (wm * 32 + mi * 16 + g) * 144 + koff;
                af[mi][0] = lds32(rb);
                af[mi][1] = lds32(rb + 8 * 144);
                af[mi][2] = lds32(rb + 16);
                af[mi][3] = lds32(rb + 8 * 144 + 16);
            }
            #pragma unroll
            for (int ni = 0; ni < 8; ni++) {
                const uint32_t nb = sbb + (wn * 64 + ni * 8 + g) * 144 + koff;
                bf[ni][0] = lds32(nb);
                bf[ni][1] = lds32(nb + 16);
            }
            #pragma unroll
            for (int mi = 0; mi < 2; mi++)
                #pragma unroll
                for (int ni = 0; ni < 8; ni++)
                    mma16816(acc[mi][ni], af[mi], bf[ni]);
        }
    };

    // double-buffered cp.async pipeline
    stage(0, 0);
    for (int kt = 0; kt < ktiles; kt++) {
        const int s = kt & 1;
        if (kt + 1 < ktiles) {
            stage(kt + 1, s ^ 1);
            asm volatile("cp.async.wait_group 1;" ::: "memory");
        } else {
            asm volatile("cp.async.wait_group 0;" ::: "memory");
        }
        __syncthreads();
        compute(s);
        __syncthreads();
    }

    // ------------------------------- epilogue -------------------------------
    if (OUT == 0) {
        float* C = (float*)Cptr;
        #pragma unroll
        for (int mi = 0; mi < 2; mi++) {
            const int m = row0 + wm * 32 + mi * 16 + g;
            #pragma unroll
            for (int ni = 0; ni < 8; ni++) {
                const int col = col0 + wn * 64 + ni * 8 + 2 * c;
                float2 o0 = make_float2(acc[mi][ni][0] * scale, acc[mi][ni][1] * scale);
                float2 o1 = make_float2(acc[mi][ni][2] * scale, acc[mi][ni][3] * scale);
                *(float2*)(C + (size_t)m       * ldc + col) = o0;
                *(float2*)(C + (size_t)(m + 8) * ldc + col) = o1;
            }
        }
    } else if (OUT == 1) {
        __half* C = (__half*)Cptr;
        #pragma unroll
        for (int mi = 0; mi < 2; mi++) {
            const int m = row0 + wm * 32 + mi * 16 + g;
            #pragma unroll
            for (int ni = 0; ni < 8; ni++) {
                const int col = col0 + wn * 64 + ni * 8 + 2 * c;
                const float b0 = bias[col], b1 = bias[col + 1];
                __half2 h0 = __floats2half2_rn(acc[mi][ni][0] + b0, acc[mi][ni][1] + b1);
                __half2 h1 = __floats2half2_rn(acc[mi][ni][2] + b0, acc[mi][ni][3] + b1);
                *(__half2*)(C + (size_t)m       * ldc + col) = h0;
                *(__half2*)(C + (size_t)(m + 8) * ldc + col) = h1;
            }
        }
    } else {
        // V^T: transpose 128x128 tile through smem, then coalesced 16B stores
        #pragma unroll
        for (int mi = 0; mi < 2; mi++) {
            const int ml = wm * 32 + mi * 16 + g;
            #pragma unroll
            for (int ni = 0; ni < 8; ni++) {
                const int nl = wn * 64 + ni * 8 + 2 * c;
                const float b0 = bias[col0 + nl], b1 = bias[col0 + nl + 1];
                *(__half*)(dsm + ((nl    ) * TSTR + ml    ) * 2) = __float2half_rn(acc[mi][ni][0] + b0);
                *(__half*)(dsm + ((nl + 1) * TSTR + ml    ) * 2) = __float2half_rn(acc[mi][ni][1] + b1);
                *(__half*)(dsm + ((nl    ) * TSTR + ml + 8) * 2) = __float2half_rn(acc[mi][ni][2] + b0);
                *(__half*)(dsm + ((nl + 1) * TSTR + ml + 8) * 2) = __float2half_rn(acc[mi][ni][3] + b1);
            }
        }
        __syncthreads();
        const int bb = row0 >> 11;          // batch
        const int t0 = row0 & 2047;         // t offset
        __half* C = (__half*)Cptr;
        #pragma unroll
        for (int i = 0; i < 8; i++) {
            const int idx = i * 256 + tid;  // 0..2047
            const int n   = idx >> 4;       // 0..127 (h within tile)
            const int ch  = idx & 15;       // 8-half chunk along t
            uint4 v = *(const uint4*)(dsm + (n * TSTR + ch * 8) * 2);
            *(uint4*)(C + ((size_t)bb * H_ + col0 + n) * T_ + t0 + ch * 8) = v;
        }
    }
}

// ---------------------------------------------------------------------------
// Pre-pass: x fp32 -> fp16
// ---------------------------------------------------------------------------
__global__ void __launch_bounds__(256)
convert_x(const float* __restrict__ x)
{
    const size_t i = ((size_t)blockIdx.x * 256 + threadIdx.x) * 8;
    float4 a = *(const float4*)(x + i);
    float4 b = *(const float4*)(x + i + 4);
    __half2 h[4] = { __floats2half2_rn(a.x, a.y), __floats2half2_rn(a.z, a.w),
                     __floats2half2_rn(b.x, b.y), __floats2half2_rn(b.z, b.w) };
    *(uint4*)(g_xh + i) = *(uint4*)h;
}

// ---------------------------------------------------------------------------
// Pre-pass: W [C,H] fp32 -> W^T [H,C] fp16 (z = 0,1,2 for Wq,Wk,Wv)
// ---------------------------------------------------------------------------
__global__ void __launch_bounds__(256)
transpose_w(const float* __restrict__ Wq, const float* __restrict__ Wk,
            const float* __restrict__ Wv)
{
    const float* W = (blockIdx.z == 0) ? Wq : (blockIdx.z == 1) ? Wk : Wv;
    __half* O = g_wth + (size_t)blockIdx.z * H_ * C_;
    __shared__ float tile[32][33];
    const int h0 = blockIdx.x * 32, c0 = blockIdx.y * 32;
    const int tx = threadIdx.x & 31, ty = threadIdx.x >> 5;
    #pragma unroll
    for (int i = ty; i < 32; i += 8)
        tile[i][tx] = W[(size_t)(c0 + i) * H_ + h0 + tx];
    __syncthreads();
    #pragma unroll
    for (int i = ty; i < 32; i += 8)
        O[(size_t)(h0 + i) * C_ + c0 + tx] = __float2half_rn(tile[tx][i]);
}

// ---------------------------------------------------------------------------
// 1) QKV projections (z=0 Q, z=1 K, z=2 V-transposed)
// ---------------------------------------------------------------------------
__global__ void __launch_bounds__(NTHREADS)
qkv_kernel(const float* __restrict__ bq, const float* __restrict__ bk,
           const float* __restrict__ bv)
{
    const int z = blockIdx.z;
    const __half* Wt = g_wth + (size_t)z * H_ * C_;
    const int row0 = blockIdx.y * 128;
    const int col0 = blockIdx.x * 128;
    if (z == 0)
        gemm_h<1>(g_xh, C_, Wt, C_, g_qh, H_, row0, col0, C_/BKH, bq, 1.0f);
    else if (z == 1)
        gemm_h<1>(g_xh, C_, Wt, C_, g_kh, H_, row0, col0, C_/BKH, bk, 1.0f);
    else
        gemm_h<2>(g_xh, C_, Wt, C_, g_vth, 0, row0, col0, C_/BKH, bv, 1.0f);
}

// ---------------------------------------------------------------------------
// 2) S = scale * Q.K^T per batch (skip blocks above the diagonal)
// ---------------------------------------------------------------------------
__global__ void __launch_bounds__(NTHREADS)
qk_kernel()
{
    const int b = blockIdx.z;
    const int row0 = blockIdx.y * 128, col0 = blockIdx.x * 128;
    if (col0 > row0) return;
    gemm_h<0>(g_qh + (size_t)b * T_ * H_, H_,
              g_kh + (size_t)b * T_ * H_, H_,
              g_s  + (size_t)b * T_ * T_, T_,
              row0, col0, H_/BKH, nullptr, SCALE_);
}

// ---------------------------------------------------------------------------
// 3) Causal softmax: reads fp32 S, writes fp16 P (zero-filled past diagonal)
// ---------------------------------------------------------------------------
__global__ void __launch_bounds__(NTHREADS)
softmax_kernel()
{
    const int i = blockIdx.x, b = blockIdx.y;
    const float* row = g_s + ((size_t)b * T_ + i) * T_;
    __half* prow     = g_p + ((size_t)b * T_ + i) * T_;
    const int n = i + 1, tid = threadIdx.x;
    __shared__ float red[8];
    __shared__ float bcv;

    float m = -1e30f;
    for (int j = tid; j < n; j += NTHREADS) m = fmaxf(m, row[j]);
    #pragma unroll
    for (int o = 16; o; o >>= 1) m = fmaxf(m, __shfl_xor_sync(0xffffffffu, m, o));
    if ((tid & 31) == 0) red[tid >> 5] = m;
    __syncthreads();
    if (tid == 0) {
        float v = red[0];
        #pragma unroll
        for (int w = 1; w < 8; w++) v = fmaxf(v, red[w]);
        bcv = v;
    }
    __syncthreads();
    m = bcv;

    float s = 0.0f;
    for (int j = tid; j < n; j += NTHREADS) s += __expf(row[j] - m);
    #pragma unroll
    for (int o = 16; o; o >>= 1) s += __shfl_xor_sync(0xffffffffu, s, o);
    __syncthreads();
    if ((tid & 31) == 0) red[tid >> 5] = s;
    __syncthreads();
    if (tid == 0) {
        float v = 0.0f;
        #pragma unroll
        for (int w = 0; w < 8; w++) v += red[w];
        bcv = 1.0f / v;
    }
    __syncthreads();
    const float inv = bcv;
    for (int j = tid; j < T_; j += NTHREADS)
        prow[j] = __float2half_rn((j < n) ? __expf(row[j] - m) * inv : 0.0f);
}

// ---------------------------------------------------------------------------
// 4) O = P.V per batch (NT with V^T; k truncated past the diagonal block)
// ---------------------------------------------------------------------------
__global__ void __launch_bounds__(NTHREADS)
pv_kernel(float* __restrict__ out)
{
    const int b = blockIdx.z;
    const int row0 = blockIdx.y * 128, col0 = blockIdx.x * 128;
    gemm_h<0>(g_p   + (size_t)b * T_ * T_, T_,
              g_vth + (size_t)b * H_ * T_, T_,
              out   + (size_t)b * T_ * H_, H_,
              row0, col0, (row0 + 128) / BKH, nullptr, 1.0f);
}

// ---------------------------------------------------------------------------
extern "C" void kernel_launch(void* const* d_in, const int* in_sizes, int n_in,
                              void* d_out, int out_size)
{
    const float* x  = (const float*)d_in[0];
    const float* Wq = (const float*)d_in[1];
    const float* bq = (const float*)d_in[2];
    const float* Wk = (const float*)d_in[3];
    const float* bk = (const float*)d_in[4];
    const float* Wv = (const float*)d_in[5];
    const float* bv = (const float*)d_in[6];
    float* out = (float*)d_out;

    static int smem_set = 0;
    if (!smem_set) {
        cudaFuncSetAttribute(qkv_kernel, cudaFuncAttributeMaxDynamicSharedMemorySize, SMEM_BYTES);
        cudaFuncSetAttribute(qk_kernel,  cudaFuncAttributeMaxDynamicSharedMemorySize, SMEM_BYTES);
        cudaFuncSetAttribute(pv_kernel,  cudaFuncAttributeMaxDynamicSharedMemorySize, SMEM_BYTES);
        smem_set = 1;
    }

    convert_x  <<<dim3((M_*(size_t)C_)/2048), dim3(256)>>>(x);
    transpose_w<<<dim3(H_/32, C_/32, 3), dim3(256)>>>(Wq, Wk, Wv);
    qkv_kernel <<<dim3(H_/128, M_/128, 3), dim3(NTHREADS), SMEM_BYTES>>>(bq, bk, bv);
    qk_kernel  <<<dim3(T_/128, T_/128, B_), dim3(NTHREADS), SMEM_BYTES>>>();
    softmax_kernel<<<dim3(T_, B_), dim3(NTHREADS)>>>();
    pv_kernel  <<<dim3(H_/128, T_/128, B_), dim3(NTHREADS), SMEM_BYTES>>>(out);
}